// round 1
// baseline (speedup 1.0000x reference)
#include <cuda_runtime.h>

// Problem dims (fixed by the dataset)
#define BB   16
#define LL   512
#define CC   256
#define MEL  4096
#define TL   64      // L-tile per conv block
#define NTHR 256

// Scratch (allocations are forbidden; __device__ globals are the sanctioned path)
__device__ float g_h1[BB * LL * CC];   // LN1 output, input to conv2
__device__ int   g_cum[BB * LL];       // per-batch inclusive cumsum of durations

// ---------------------------------------------------------------------------
// Packed fp32x2 helpers (Blackwell f32x2 pipe: 2x fp32 FMA throughput)
// ---------------------------------------------------------------------------
__device__ __forceinline__ unsigned long long pack2(float lo, float hi) {
    unsigned long long r;
    asm("mov.b64 %0, {%1, %2};" : "=l"(r) : "f"(lo), "f"(hi));
    return r;
}
__device__ __forceinline__ void ffma2(unsigned long long& d,
                                      unsigned long long a,
                                      unsigned long long b) {
    asm("fma.rn.f32x2 %0, %1, %2, %0;" : "+l"(d) : "l"(a), "l"(b));
}
__device__ __forceinline__ float lo32(unsigned long long v) {
    return __uint_as_float((unsigned)(v & 0xffffffffull));
}
__device__ __forceinline__ float hi32(unsigned long long v) {
    return __uint_as_float((unsigned)(v >> 32));
}

// ---------------------------------------------------------------------------
// Fused conv1d(K=3, SAME) + bias + ReLU + LayerNorm  [+ final linear if FINAL]
// One block computes a full [TL x 256] output tile so LN can reduce in-block.
// Thread layout: tx = tid&15 (16 F-groups), ty = tid>>4 (16 L-groups of 4 rows)
// Thread's 16 F columns: f = j*64 + tx*4 + jj  (j=0..3, jj=0..3)
// ---------------------------------------------------------------------------
template <bool FINAL>
__global__ void __launch_bounds__(NTHR, 1)
conv_ln_kernel(const float* __restrict__ xin,    // [B,L,256] (only used if !FINAL)
               const float* __restrict__ w,      // [3,256,256]
               const float* __restrict__ bias,   // [256]
               const float* __restrict__ gamma,  // [256]
               const float* __restrict__ beta,   // [256]
               const float* __restrict__ linw,   // [256] (FINAL only)
               const float* __restrict__ linb,   // [1]   (FINAL only)
               float* __restrict__ predout)      // [B,L] (FINAL only)
{
    __shared__ __align__(16) float As[16][68];    // [d][l] transposed, padded
    __shared__ __align__(16) float Ws[16][256];   // [d][f]

    const int tid = threadIdx.x;
    const int tx = tid & 15;
    const int ty = tid >> 4;
    const int b  = blockIdx.y;
    const int l0 = blockIdx.x * TL;

    const float* inb = (FINAL ? (const float*)g_h1 : xin) + (size_t)b * LL * CC;

    // 32 packed accumulators = 4 L-rows x 16 F-cols
    unsigned long long acc[4][8];
#pragma unroll
    for (int r = 0; r < 4; r++)
#pragma unroll
        for (int p = 0; p < 8; p++) acc[r][p] = 0ull;

    for (int k = 0; k < 3; k++) {
        for (int dc = 0; dc < CC; dc += 16) {
            __syncthreads();
            // Stage A: As[d][l] = in[b, l0+l+k-1, dc+d] (zero-pad OOB rows)
#pragma unroll
            for (int p = 0; p < 4; p++) {
                int l = ty + p * 16;
                int row = l0 + l + k - 1;
                float v = (row >= 0 && row < LL) ? inb[row * CC + dc + tx] : 0.f;
                As[tx][l] = v;
            }
            // Stage W: Ws[d][f] = w[k, dc+d, f] (coalesced float4)
#pragma unroll
            for (int r = 0; r < 4; r++) {
                int f4 = tid + r * NTHR;           // 0..1023
                int drow = f4 >> 6;
                int c4 = f4 & 63;
                *(float4*)(&Ws[drow][c4 * 4]) =
                    *(const float4*)(w + ((size_t)(k * CC + dc + drow)) * CC + c4 * 4);
            }
            __syncthreads();

#pragma unroll
            for (int i = 0; i < 16; i++) {
                float4 av = *(const float4*)(&As[i][ty * 4]);
                unsigned long long a0 = pack2(av.x, av.x);
                unsigned long long a1 = pack2(av.y, av.y);
                unsigned long long a2 = pack2(av.z, av.z);
                unsigned long long a3 = pack2(av.w, av.w);
#pragma unroll
                for (int j = 0; j < 4; j++) {
                    ulonglong2 wv = *(const ulonglong2*)(&Ws[i][j * 64 + tx * 4]);
                    ffma2(acc[0][2 * j],     a0, wv.x);
                    ffma2(acc[0][2 * j + 1], a0, wv.y);
                    ffma2(acc[1][2 * j],     a1, wv.x);
                    ffma2(acc[1][2 * j + 1], a1, wv.y);
                    ffma2(acc[2][2 * j],     a2, wv.x);
                    ffma2(acc[2][2 * j + 1], a2, wv.y);
                    ffma2(acc[3][2 * j],     a3, wv.x);
                    ffma2(acc[3][2 * j + 1], a3, wv.y);
                }
            }
        }
    }

    // Per-thread channel metadata for its 16 f columns
    float bias_v[16], g_v[16], be_v[16], lw_v[16];
#pragma unroll
    for (int p = 0; p < 8; p++) {
        int f = (p >> 1) * 64 + tx * 4 + ((p & 1) << 1);
        bias_v[2 * p] = bias[f];     bias_v[2 * p + 1] = bias[f + 1];
        g_v[2 * p]    = gamma[f];    g_v[2 * p + 1]    = gamma[f + 1];
        be_v[2 * p]   = beta[f];     be_v[2 * p + 1]   = beta[f + 1];
        if (FINAL) { lw_v[2 * p] = linw[f]; lw_v[2 * p + 1] = linw[f + 1]; }
    }

    const float lbv = FINAL ? linb[0] : 0.f;

#pragma unroll
    for (int rr = 0; rr < 4; rr++) {
        float v[16];
        float s = 0.f, s2 = 0.f;
#pragma unroll
        for (int p = 0; p < 8; p++) {
            float a = fmaxf(lo32(acc[rr][p]) + bias_v[2 * p], 0.f);
            float c = fmaxf(hi32(acc[rr][p]) + bias_v[2 * p + 1], 0.f);
            v[2 * p] = a; v[2 * p + 1] = c;
            s += a + c;
            s2 += a * a + c * c;
        }
        // reduce across the 16 tx lanes (lane bits 0..3)
#pragma unroll
        for (int m = 1; m < 16; m <<= 1) {
            s  += __shfl_xor_sync(0xffffffffu, s, m);
            s2 += __shfl_xor_sync(0xffffffffu, s2, m);
        }
        float mu  = s * (1.f / 256.f);
        float var = s2 * (1.f / 256.f) - mu * mu;
        float rs  = rsqrtf(var + 1e-5f);

        int l = l0 + ty * 4 + rr;
        if (!FINAL) {
            float* orow = g_h1 + ((size_t)b * LL + l) * CC;
#pragma unroll
            for (int j = 0; j < 4; j++) {
                float4 o;
                o.x = (v[4 * j]     - mu) * rs * g_v[4 * j]     + be_v[4 * j];
                o.y = (v[4 * j + 1] - mu) * rs * g_v[4 * j + 1] + be_v[4 * j + 1];
                o.z = (v[4 * j + 2] - mu) * rs * g_v[4 * j + 2] + be_v[4 * j + 2];
                o.w = (v[4 * j + 3] - mu) * rs * g_v[4 * j + 3] + be_v[4 * j + 3];
                *(float4*)(orow + j * 64 + tx * 4) = o;
            }
        } else {
            float d = 0.f;
#pragma unroll
            for (int q = 0; q < 16; q++)
                d += ((v[q] - mu) * rs * g_v[q] + be_v[q]) * lw_v[q];
#pragma unroll
            for (int m = 1; m < 16; m <<= 1)
                d += __shfl_xor_sync(0xffffffffu, d, m);
            if (tx == 0) predout[b * LL + l] = d + lbv;
        }
    }
}

// ---------------------------------------------------------------------------
// Inclusive cumsum of durations, one block per batch (Hillis-Steele in smem)
// ---------------------------------------------------------------------------
__global__ void __launch_bounds__(512) cumsum_kernel(const int* __restrict__ dur)
{
    __shared__ int s[LL];
    int b = blockIdx.x, tid = threadIdx.x;
    s[tid] = dur[b * LL + tid];
    __syncthreads();
    for (int off = 1; off < LL; off <<= 1) {
        int v = (tid >= off) ? s[tid - off] : 0;
        __syncthreads();
        s[tid] += v;
        __syncthreads();
    }
    g_cum[b * LL + tid] = s[tid];
}

// ---------------------------------------------------------------------------
// Length regulation: per block, 16 output frames x 256 channels.
// Binary-search token index in smem cumsum, gather x row (or zero).
// ---------------------------------------------------------------------------
__global__ void __launch_bounds__(256) regulate_kernel(const float* __restrict__ x,
                                                       float* __restrict__ outp)
{
    __shared__ int scum[LL];
    __shared__ int sidx[16];
    const int tid = threadIdx.x;
    const int b  = blockIdx.y;
    const int t0 = blockIdx.x * 16;

    const int* cb = g_cum + b * LL;
    scum[tid]       = cb[tid];
    scum[tid + 256] = cb[tid + 256];
    __syncthreads();

    if (tid < 16) {
        int t = t0 + tid;
        int total = scum[LL - 1];
        int lo = 0, hi = LL;
        while (lo < hi) {
            int mid = (lo + hi) >> 1;
            if (scum[mid] <= t) lo = mid + 1; else hi = mid;
        }
        sidx[tid] = (t < total) ? min(lo, LL - 1) : -1;
    }
    __syncthreads();

#pragma unroll
    for (int r = 0; r < 4; r++) {
        int q = tid + r * 256;          // 0..1023 float4 slots
        int fr = q >> 6;                // frame within block
        int c4 = q & 63;                // float4 column
        int idx = sidx[fr];
        float4 val = make_float4(0.f, 0.f, 0.f, 0.f);
        if (idx >= 0)
            val = *(const float4*)(x + ((size_t)b * LL + idx) * CC + c4 * 4);
        *(float4*)(outp + ((size_t)b * MEL + t0 + fr) * CC + c4 * 4) = val;
    }
}

// ---------------------------------------------------------------------------
extern "C" void kernel_launch(void* const* d_in, const int* in_sizes, int n_in,
                              void* d_out, int out_size)
{
    const float* x    = (const float*)d_in[0];
    const int*   dur  = (const int*)d_in[1];
    const float* c1w  = (const float*)d_in[2];
    const float* c1b  = (const float*)d_in[3];
    const float* ln1g = (const float*)d_in[4];
    const float* ln1b = (const float*)d_in[5];
    const float* c2w  = (const float*)d_in[6];
    const float* c2b  = (const float*)d_in[7];
    const float* ln2g = (const float*)d_in[8];
    const float* ln2b = (const float*)d_in[9];
    const float* linw = (const float*)d_in[10];
    const float* linb = (const float*)d_in[11];

    float* out  = (float*)d_out;
    float* pred = out + (size_t)BB * MEL * CC;   // regulated first, then pred

    cumsum_kernel<<<BB, 512>>>(dur);

    dim3 cgrid(LL / TL, BB);
    conv_ln_kernel<false><<<cgrid, NTHR>>>(x, c1w, c1b, ln1g, ln1b,
                                           nullptr, nullptr, nullptr);
    conv_ln_kernel<true><<<cgrid, NTHR>>>(x, c2w, c2b, ln2g, ln2b,
                                          linw, linb, pred);

    dim3 rgrid(MEL / 16, BB);
    regulate_kernel<<<rgrid, 256>>>(x, out);
}

// round 3
// speedup vs baseline: 1.9753x; 1.9753x over previous
#include <cuda_runtime.h>
#include <cstdint>

#define BB   16
#define LL   512
#define CC   256
#define MEL  4096

// ---------------------------------------------------------------------------
// Scratch (__device__ globals — allocations are forbidden)
// ---------------------------------------------------------------------------
__device__ float g_h1[BB * LL * CC];   // LN1 output -> conv2 input
__device__ int   g_cum[BB * LL];       // per-batch cumsum of durations

// ---------------------------------------------------------------------------
// tf32 helpers (all arch-generic PTX, sm_80+)
// ---------------------------------------------------------------------------
__device__ __forceinline__ uint32_t f2tf(float f) {
    uint32_t u;
    asm("cvt.rna.tf32.f32 %0, %1;" : "=r"(u) : "f"(f));
    return u;
}

__device__ __forceinline__ void mma_tf32(float* d, const uint32_t* a, const uint32_t* b) {
    asm volatile(
        "mma.sync.aligned.m16n8k8.row.col.f32.tf32.tf32.f32 "
        "{%0,%1,%2,%3}, {%4,%5,%6,%7}, {%8,%9}, {%0,%1,%2,%3};"
        : "+f"(d[0]), "+f"(d[1]), "+f"(d[2]), "+f"(d[3])
        : "r"(a[0]), "r"(a[1]), "r"(a[2]), "r"(a[3]), "r"(b[0]), "r"(b[1]));
}

// smem strides (floats). Chosen so fragment-load bank = 8*q + g (+const):
// conflict-free across a warp.  A: k-major [32 c][72], B: [32 c][264].
#define SA_STR 72
#define SB_STR 264

// ---------------------------------------------------------------------------
// Fused conv1d(K=3,SAME) + bias + ReLU + LayerNorm [+ linear head if FINAL]
// CTA = [64 l x 256 f]; 8 warps, warp tile 64x32 (n0 = warp*32).
// ---------------------------------------------------------------------------
template <bool FINAL>
__global__ void __launch_bounds__(256, 1)
conv_mma_kernel(const float* __restrict__ xin,     // conv input (g_h1 if FINAL)
                const float* __restrict__ w,       // [3,256,256]
                const float* __restrict__ bias,
                const float* __restrict__ gamma,
                const float* __restrict__ beta,
                const float* __restrict__ linw,
                const float* __restrict__ linb,
                float* __restrict__ predout)
{
    __shared__ uint32_t sA[32 * SA_STR];           //  9216 B
    __shared__ uint32_t sB[32 * SB_STR];           // 33792 B

    const int tid  = threadIdx.x;
    const int warp = tid >> 5, lane = tid & 31;
    const int g = lane >> 2, q = lane & 3;
    const int n0 = warp * 32;
    const int b  = blockIdx.y;
    const int l0 = blockIdx.x * 64;

    const float* inb = (FINAL ? (const float*)g_h1 : xin) + (size_t)b * LL * CC;

    float acc[4][4][4];                            // [mt][nt][creg]
#pragma unroll
    for (int mt = 0; mt < 4; mt++)
#pragma unroll
        for (int nt = 0; nt < 4; nt++)
#pragma unroll
            for (int r = 0; r < 4; r++) acc[mt][nt][r] = 0.f;

    for (int it = 0; it < 24; it++) {
        const int k = it >> 3, cc = it & 7;
        __syncthreads();
        // ---- stage A: in[l0-1+k .. ][cc*32..] -> sA[c][r] (k-major, tf32) ----
#pragma unroll
        for (int i = 0; i < 2; i++) {
            int idx = tid + i * 256;               // 0..511
            int r = idx & 63, c4 = idx >> 6;       // r row-in-tile, c4 float4 grp
            int row = l0 + r + k - 1;
            float4 v = make_float4(0.f, 0.f, 0.f, 0.f);
            if (row >= 0 && row < LL)
                v = *(const float4*)(inb + (size_t)row * CC + cc * 32 + c4 * 4);
            sA[(c4 * 4 + 0) * SA_STR + r] = f2tf(v.x);
            sA[(c4 * 4 + 1) * SA_STR + r] = f2tf(v.y);
            sA[(c4 * 4 + 2) * SA_STR + r] = f2tf(v.z);
            sA[(c4 * 4 + 3) * SA_STR + r] = f2tf(v.w);
        }
        // ---- stage B: w[k][cc*32+c][f] -> sB[c][f] (tf32) ----
        {
            const float* wsrc = w + ((size_t)k * CC + cc * 32) * CC;
#pragma unroll
            for (int i = 0; i < 8; i++) {
                int idx = tid + i * 256;           // 0..2047 float4 groups
                int c = idx >> 6, f4 = idx & 63;
                float4 v = *(const float4*)(wsrc + (size_t)c * CC + f4 * 4);
                uint32_t* dst = sB + c * SB_STR + f4 * 4;
                dst[0] = f2tf(v.x); dst[1] = f2tf(v.y);
                dst[2] = f2tf(v.z); dst[3] = f2tf(v.w);
            }
        }
        __syncthreads();
        // ---- compute: 4 k-steps of 8 ----
#pragma unroll
        for (int ks = 0; ks < 4; ks++) {
            const int k0 = ks * 8;
            uint32_t af[4][4], bf[4][2];
#pragma unroll
            for (int mt = 0; mt < 4; mt++) {
                af[mt][0] = sA[(k0 + q) * SA_STR + mt * 16 + g];
                af[mt][1] = sA[(k0 + q) * SA_STR + mt * 16 + g + 8];
                af[mt][2] = sA[(k0 + q + 4) * SA_STR + mt * 16 + g];
                af[mt][3] = sA[(k0 + q + 4) * SA_STR + mt * 16 + g + 8];
            }
#pragma unroll
            for (int nt = 0; nt < 4; nt++) {
                bf[nt][0] = sB[(k0 + q) * SB_STR + n0 + nt * 8 + g];
                bf[nt][1] = sB[(k0 + q + 4) * SB_STR + n0 + nt * 8 + g];
            }
#pragma unroll
            for (int mt = 0; mt < 4; mt++)
#pragma unroll
                for (int nt = 0; nt < 4; nt++)
                    mma_tf32(acc[mt][nt], af[mt], bf[nt]);
        }
    }
    __syncthreads();   // before overlaying reduction buffers onto sA

    // ---- epilogue: bias + ReLU + LayerNorm (fused), optional linear head ----
    // this thread's 8 columns (same for all its rows)
    float bi[8], ga[8], be[8], lw[8];
#pragma unroll
    for (int nt = 0; nt < 4; nt++)
#pragma unroll
        for (int j = 0; j < 2; j++) {
            int c = n0 + nt * 8 + 2 * q + j;
            bi[nt * 2 + j] = __ldg(bias + c);
            ga[nt * 2 + j] = __ldg(gamma + c);
            be[nt * 2 + j] = __ldg(beta + c);
            if (FINAL) lw[nt * 2 + j] = __ldg(linw + c);
        }

    float v[4][2][8];                              // [mt][h][col]
    float2* red   = (float2*)sA;                   // [64 rows][8 warps]
    float2* stats = (float2*)sA + 512;             // [64 rows] (mu, rs)

#pragma unroll
    for (int mt = 0; mt < 4; mt++)
#pragma unroll
        for (int h = 0; h < 2; h++) {
            float s = 0.f, s2 = 0.f;
#pragma unroll
            for (int nt = 0; nt < 4; nt++)
#pragma unroll
                for (int j = 0; j < 2; j++) {
                    float x = acc[mt][nt][h * 2 + j] + bi[nt * 2 + j];
                    x = fmaxf(x, 0.f);
                    v[mt][h][nt * 2 + j] = x;
                    s += x; s2 += x * x;
                }
            // reduce over the 4 lanes sharing this row (q bits)
            s  += __shfl_xor_sync(0xffffffffu, s, 1);
            s2 += __shfl_xor_sync(0xffffffffu, s2, 1);
            s  += __shfl_xor_sync(0xffffffffu, s, 2);
            s2 += __shfl_xor_sync(0xffffffffu, s2, 2);
            if (q == 0) {
                int r = mt * 16 + g + 8 * h;
                red[r * 8 + warp] = make_float2(s, s2);
            }
        }
    __syncthreads();
    if (tid < 64) {
        float s = 0.f, s2 = 0.f;
#pragma unroll
        for (int wv = 0; wv < 8; wv++) {
            float2 p = red[tid * 8 + wv];
            s += p.x; s2 += p.y;
        }
        float mu = s * (1.f / 256.f);
        float var = s2 * (1.f / 256.f) - mu * mu;
        stats[tid] = make_float2(mu, rsqrtf(var + 1e-5f));
    }
    __syncthreads();

    if (!FINAL) {
#pragma unroll
        for (int mt = 0; mt < 4; mt++)
#pragma unroll
            for (int h = 0; h < 2; h++) {
                int r = mt * 16 + g + 8 * h;
                float2 st = stats[r];
                float* orow = g_h1 + ((size_t)b * LL + l0 + r) * CC;
#pragma unroll
                for (int nt = 0; nt < 4; nt++) {
                    float2 o;
                    o.x = (v[mt][h][nt * 2]     - st.x) * st.y * ga[nt * 2]     + be[nt * 2];
                    o.y = (v[mt][h][nt * 2 + 1] - st.x) * st.y * ga[nt * 2 + 1] + be[nt * 2 + 1];
                    *(float2*)(orow + n0 + nt * 8 + 2 * q) = o;
                }
            }
    } else {
        float* dred = (float*)(sB);                // [64 rows][8 warps]
#pragma unroll
        for (int mt = 0; mt < 4; mt++)
#pragma unroll
            for (int h = 0; h < 2; h++) {
                int r = mt * 16 + g + 8 * h;
                float2 st = stats[r];
                float d = 0.f;
#pragma unroll
                for (int p = 0; p < 8; p++)
                    d += ((v[mt][h][p] - st.x) * st.y * ga[p] + be[p]) * lw[p];
                d += __shfl_xor_sync(0xffffffffu, d, 1);
                d += __shfl_xor_sync(0xffffffffu, d, 2);
                if (q == 0) dred[r * 8 + warp] = d;
            }
        __syncthreads();
        if (tid < 64) {
            float d = 0.f;
#pragma unroll
            for (int wv = 0; wv < 8; wv++) d += dred[tid * 8 + wv];
            predout[b * LL + l0 + tid] = d + __ldg(linb);
        }
    }
}

// ---------------------------------------------------------------------------
// cumsum + regulate (unchanged — regulate already ~L2-bound at 15us)
// ---------------------------------------------------------------------------
__global__ void __launch_bounds__(512) cumsum_kernel(const int* __restrict__ dur)
{
    __shared__ int s[LL];
    int b = blockIdx.x, tid = threadIdx.x;
    s[tid] = dur[b * LL + tid];
    __syncthreads();
    for (int off = 1; off < LL; off <<= 1) {
        int v = (tid >= off) ? s[tid - off] : 0;
        __syncthreads();
        s[tid] += v;
        __syncthreads();
    }
    g_cum[b * LL + tid] = s[tid];
}

__global__ void __launch_bounds__(256) regulate_kernel(const float* __restrict__ x,
                                                       float* __restrict__ outp)
{
    __shared__ int scum[LL];
    __shared__ int sidx[16];
    const int tid = threadIdx.x;
    const int b = blockIdx.y;
    const int t0 = blockIdx.x * 16;

    const int* cb = g_cum + b * LL;
    scum[tid] = cb[tid];
    scum[tid + 256] = cb[tid + 256];
    __syncthreads();

    if (tid < 16) {
        int t = t0 + tid;
        int total = scum[LL - 1];
        int lo = 0, hi = LL;
        while (lo < hi) {
            int mid = (lo + hi) >> 1;
            if (scum[mid] <= t) lo = mid + 1; else hi = mid;
        }
        sidx[tid] = (t < total) ? min(lo, LL - 1) : -1;
    }
    __syncthreads();

#pragma unroll
    for (int r = 0; r < 4; r++) {
        int qq = tid + r * 256;
        int fr = qq >> 6, c4 = qq & 63;
        int idx = sidx[fr];
        float4 val = make_float4(0.f, 0.f, 0.f, 0.f);
        if (idx >= 0)
            val = *(const float4*)(x + ((size_t)b * LL + idx) * CC + c4 * 4);
        *(float4*)(outp + ((size_t)b * MEL + t0 + fr) * CC + c4 * 4) = val;
    }
}

// ---------------------------------------------------------------------------
extern "C" void kernel_launch(void* const* d_in, const int* in_sizes, int n_in,
                              void* d_out, int out_size)
{
    const float* x    = (const float*)d_in[0];
    const int*   dur  = (const int*)d_in[1];
    const float* c1w  = (const float*)d_in[2];
    const float* c1b  = (const float*)d_in[3];
    const float* ln1g = (const float*)d_in[4];
    const float* ln1b = (const float*)d_in[5];
    const float* c2w  = (const float*)d_in[6];
    const float* c2b  = (const float*)d_in[7];
    const float* ln2g = (const float*)d_in[8];
    const float* ln2b = (const float*)d_in[9];
    const float* linw = (const float*)d_in[10];
    const float* linb = (const float*)d_in[11];

    float* out  = (float*)d_out;
    float* pred = out + (size_t)BB * MEL * CC;

    cumsum_kernel<<<BB, 512>>>(dur);

    dim3 cgrid(LL / 64, BB);
    conv_mma_kernel<false><<<cgrid, 256>>>(x, c1w, c1b, ln1g, ln1b,
                                           nullptr, nullptr, nullptr);
    conv_mma_kernel<true><<<cgrid, 256>>>(nullptr, c2w, c2b, ln2g, ln2b,
                                          linw, linb, pred);

    dim3 rgrid(MEL / 16, BB);
    regulate_kernel<<<rgrid, 256>>>(x, out);
}

// round 4
// speedup vs baseline: 1.9823x; 1.0035x over previous
#include <cuda_runtime.h>
#include <cstdint>

#define BB   16
#define LL   512
#define CC   256
#define MEL  4096

// ---------------------------------------------------------------------------
// Scratch (__device__ globals — allocations are forbidden)
// ---------------------------------------------------------------------------
__device__ float g_h1[BB * LL * CC];          // LN1 out (tf32-rounded) -> conv2 A
__device__ int   g_cum[BB * LL];
__device__ int   g_idx[BB * MEL];             // per-frame token index (-1 invalid)
__device__ float g_wcvt[2 * 3 * CC * CC];     // RNA-rounded weights, both convs

// ---------------------------------------------------------------------------
// helpers (arch-generic PTX)
// ---------------------------------------------------------------------------
__device__ __forceinline__ uint32_t f2tf(float f) {
    uint32_t u;
    asm("cvt.rna.tf32.f32 %0, %1;" : "=r"(u) : "f"(f));
    return u;
}
__device__ __forceinline__ float f2tff(float f) { return __uint_as_float(f2tf(f)); }

__device__ __forceinline__ void mma_tf32(float* d, const uint32_t* a, const uint32_t* b) {
    asm volatile(
        "mma.sync.aligned.m16n8k8.row.col.f32.tf32.tf32.f32 "
        "{%0,%1,%2,%3}, {%4,%5,%6,%7}, {%8,%9}, {%0,%1,%2,%3};"
        : "+f"(d[0]), "+f"(d[1]), "+f"(d[2]), "+f"(d[3])
        : "r"(a[0]), "r"(a[1]), "r"(a[2]), "r"(a[3]), "r"(b[0]), "r"(b[1]));
}

__device__ __forceinline__ uint32_t smem_u32(const void* p) {
    uint32_t a;
    asm("{ .reg .u64 t; cvta.to.shared.u64 t, %1; cvt.u32.u64 %0, t; }"
        : "=r"(a) : "l"(p));
    return a;
}
#define CP_ASYNC16(dst, src) \
    asm volatile("cp.async.ca.shared.global [%0], [%1], 16;" :: "r"(dst), "l"(src))
#define CP_COMMIT() asm volatile("cp.async.commit_group;" ::: "memory")
#define CP_WAIT1()  asm volatile("cp.async.wait_group 1;" ::: "memory")
#define CP_WAIT0()  asm volatile("cp.async.wait_group 0;" ::: "memory")

// smem geometry (floats). Strides ≡ 8 (mod 32) -> conflict-free frag loads.
#define SA_STR 264          // A: [66 rows][256 ch]  bank = 8g + q
#define SB_STR 264          // B: [64 ch][256 f]     bank = 8q + g
#define SA_FLOATS (66 * SA_STR)          // 17424
#define SB_FLOATS (64 * SB_STR)          // 16896
#define SMEM_FLOATS (SA_FLOATS + 2 * SB_FLOATS)
#define SMEM_BYTES  (SMEM_FLOATS * 4)    // 204864

// ---------------------------------------------------------------------------
// Weight pre-round (RNA) once: g_wcvt = round_tf32(w1 ++ w2)
// ---------------------------------------------------------------------------
__global__ void __launch_bounds__(512) cvt_weights(const float* __restrict__ w1,
                                                   const float* __restrict__ w2)
{
    const int n = 3 * CC * CC;                     // 196608 per conv
    int i = blockIdx.x * 512 + threadIdx.x;        // grid 192 -> 98304 threads
    g_wcvt[i]           = f2tff(w1[i]);
    g_wcvt[i + 98304]   = f2tff(w1[i + 98304]);
    g_wcvt[n + i]         = f2tff(w2[i]);
    g_wcvt[n + i + 98304] = f2tff(w2[i + 98304]);
}

// ---------------------------------------------------------------------------
// cumsum + frame->token index precompute (one block per batch)
// ---------------------------------------------------------------------------
__global__ void __launch_bounds__(512) cumsum_kernel(const int* __restrict__ dur)
{
    __shared__ int s[LL];
    int b = blockIdx.x, tid = threadIdx.x;
    s[tid] = dur[b * LL + tid];
    __syncthreads();
    for (int off = 1; off < LL; off <<= 1) {
        int v = (tid >= off) ? s[tid - off] : 0;
        __syncthreads();
        s[tid] += v;
        __syncthreads();
    }
    g_cum[b * LL + tid] = s[tid];
    int total = s[LL - 1];
#pragma unroll
    for (int r = 0; r < 8; r++) {
        int t = tid + r * 512;
        int lo = 0, hi = LL;
        while (lo < hi) {
            int mid = (lo + hi) >> 1;
            if (s[mid] <= t) lo = mid + 1; else hi = mid;
        }
        g_idx[b * MEL + t] = (t < total) ? min(lo, LL - 1) : -1;
    }
}

// ---------------------------------------------------------------------------
// Fused conv1d(K=3,SAME)+bias+ReLU+LN [+linear head if FINAL]
// CTA = [64 l x 256 f], 8 warps 64x32. A resident; B cp.async double-buffered.
// Conv1 additionally streams its share of the length-regulated output.
// ---------------------------------------------------------------------------
template <bool FINAL>
__global__ void __launch_bounds__(256, 1)
conv_mma_kernel(const float* __restrict__ xin,     // x (also regulate src)
                const float* __restrict__ bias,
                const float* __restrict__ gamma,
                const float* __restrict__ beta,
                const float* __restrict__ linw,
                const float* __restrict__ linb,
                float* __restrict__ predout,
                float* __restrict__ regout)
{
    extern __shared__ __align__(16) float smem[];
    float* sA = smem;
    float* sB[2] = { smem + SA_FLOATS, smem + SA_FLOATS + SB_FLOATS };
    const uint32_t sb_u32[2] = { smem_u32(sB[0]), smem_u32(sB[1]) };

    const int tid  = threadIdx.x;
    const int warp = tid >> 5, lane = tid & 31;
    const int g = lane >> 2, q = lane & 3;
    const int n0 = warp * 32;
    const int b  = blockIdx.y;
    const int l0 = blockIdx.x * 64;
    const int CONV = FINAL ? 1 : 0;
    const float* inb = (FINAL ? (const float*)g_h1 : xin) + (size_t)b * LL * CC;
    const float* wbase = g_wcvt + (size_t)CONV * 3 * CC * CC;

    // ---- stage B chunk 0 and 1 (cp.async), then A (resident) ----
    auto stageB = [&](int it, int buf) {
        const int k = it >> 2, c0 = (it & 3) * 64;
        const float* src = wbase + ((size_t)(k * CC + c0)) * CC;
#pragma unroll
        for (int i = 0; i < 16; i++) {
            int idx = tid + i * 256;               // 0..4095
            int c = idx >> 6, f4 = idx & 63;
            CP_ASYNC16(sb_u32[buf] + (uint32_t)(c * SB_STR + f4 * 4) * 4,
                       src + (size_t)c * CC + f4 * 4);
        }
        CP_COMMIT();
    };
    stageB(0, 0);
    stageB(1, 1);

#pragma unroll 4
    for (int i = 0; i < 17; i++) {
        int idx = tid + i * 256;                   // 0..4351, need 4224
        if (idx < 66 * 64) {
            int sr = idx >> 6, f4 = idx & 63;
            int grow = l0 + sr - 1;
            float4 v = make_float4(0.f, 0.f, 0.f, 0.f);
            if (grow >= 0 && grow < LL)
                v = *(const float4*)(inb + (size_t)grow * CC + f4 * 4);
            if (!FINAL) { v.x = f2tff(v.x); v.y = f2tff(v.y);
                          v.z = f2tff(v.z); v.w = f2tff(v.w); }
            *(float4*)(sA + sr * SA_STR + f4 * 4) = v;
        }
    }

    float acc[4][4][4];
#pragma unroll
    for (int mt = 0; mt < 4; mt++)
#pragma unroll
        for (int nt = 0; nt < 4; nt++)
#pragma unroll
            for (int r = 0; r < 4; r++) acc[mt][nt][r] = 0.f;

    for (int it = 0; it < 12; it++) {
        const int ktap = it >> 2, c0 = (it & 3) * 64;
        const int buf = it & 1;
        if (it < 11) CP_WAIT1(); else CP_WAIT0();
        __syncthreads();

        const float* bp = sB[buf];
        const float* ap = sA + (ktap + g) * SA_STR + c0 + q;
#pragma unroll
        for (int ks = 0; ks < 8; ks++) {
            uint32_t af[4][4], bf[4][2];
#pragma unroll
            for (int mt = 0; mt < 4; mt++) {
                const float* a0 = ap + mt * (16 * SA_STR) + ks * 8;
                af[mt][0] = __float_as_uint(a0[0]);
                af[mt][1] = __float_as_uint(a0[8 * SA_STR]);
                af[mt][2] = __float_as_uint(a0[4]);
                af[mt][3] = __float_as_uint(a0[8 * SA_STR + 4]);
            }
#pragma unroll
            for (int nt = 0; nt < 4; nt++) {
                bf[nt][0] = __float_as_uint(bp[(ks * 8 + q) * SB_STR + n0 + nt * 8 + g]);
                bf[nt][1] = __float_as_uint(bp[(ks * 8 + q + 4) * SB_STR + n0 + nt * 8 + g]);
            }
#pragma unroll
            for (int mt = 0; mt < 4; mt++)
#pragma unroll
                for (int nt = 0; nt < 4; nt++)
                    mma_tf32(acc[mt][nt], af[mt], bf[nt]);
        }
        __syncthreads();
        if (it + 2 < 12) stageB(it + 2, buf);

        // ---- interleaved length regulation (conv1 only) ----
        if (!FINAL) {
            int ix[11];
            float4 vv[11];
#pragma unroll
            for (int u = 0; u < 11; u++) {
                int s = it * 11 + u;
                ix[u] = -1;
                if (s < 128)
                    ix[u] = g_idx[b * MEL + blockIdx.x * 512 + ((tid + s * 256) >> 6)];
            }
#pragma unroll
            for (int u = 0; u < 11; u++) {
                vv[u] = make_float4(0.f, 0.f, 0.f, 0.f);
                if (ix[u] >= 0) {
                    int s = it * 11 + u;
                    int c4 = (tid + s * 256) & 63;
                    vv[u] = *(const float4*)(xin + ((size_t)b * LL + ix[u]) * CC + c4 * 4);
                }
            }
#pragma unroll
            for (int u = 0; u < 11; u++) {
                int s = it * 11 + u;
                if (s < 128) {
                    int j = tid + s * 256;
                    int fr = j >> 6, c4 = j & 63;
                    *(float4*)(regout + ((size_t)b * MEL + blockIdx.x * 512 + fr) * CC + c4 * 4) = vv[u];
                }
            }
        }
    }
    __syncthreads();

    // ---- epilogue: bias + ReLU + LN (fused), optional linear head ----
    float bi[8], ga[8], be[8], lw[8];
#pragma unroll
    for (int nt = 0; nt < 4; nt++)
#pragma unroll
        for (int j = 0; j < 2; j++) {
            int c = n0 + nt * 8 + 2 * q + j;
            bi[nt * 2 + j] = __ldg(bias + c);
            ga[nt * 2 + j] = __ldg(gamma + c);
            be[nt * 2 + j] = __ldg(beta + c);
            if (FINAL) lw[nt * 2 + j] = __ldg(linw + c);
        }

    float v[4][2][8];
    float2* red   = (float2*)sA;                   // [64][8]
    float2* stats = (float2*)sA + 512;             // [64]

#pragma unroll
    for (int mt = 0; mt < 4; mt++)
#pragma unroll
        for (int h = 0; h < 2; h++) {
            float s = 0.f, s2 = 0.f;
#pragma unroll
            for (int nt = 0; nt < 4; nt++)
#pragma unroll
                for (int j = 0; j < 2; j++) {
                    float x = acc[mt][nt][h * 2 + j] + bi[nt * 2 + j];
                    x = fmaxf(x, 0.f);
                    v[mt][h][nt * 2 + j] = x;
                    s += x; s2 += x * x;
                }
            s  += __shfl_xor_sync(0xffffffffu, s, 1);
            s2 += __shfl_xor_sync(0xffffffffu, s2, 1);
            s  += __shfl_xor_sync(0xffffffffu, s, 2);
            s2 += __shfl_xor_sync(0xffffffffu, s2, 2);
            if (q == 0)
                red[(mt * 16 + g + 8 * h) * 8 + warp] = make_float2(s, s2);
        }
    __syncthreads();
    if (tid < 64) {
        float s = 0.f, s2 = 0.f;
#pragma unroll
        for (int wv = 0; wv < 8; wv++) {
            float2 p = red[tid * 8 + wv];
            s += p.x; s2 += p.y;
        }
        float mu = s * (1.f / 256.f);
        float var = s2 * (1.f / 256.f) - mu * mu;
        stats[tid] = make_float2(mu, rsqrtf(var + 1e-5f));
    }
    __syncthreads();

    if (!FINAL) {
        // store tf32-pre-rounded h1 (matches round-at-load numerics)
#pragma unroll
        for (int mt = 0; mt < 4; mt++)
#pragma unroll
            for (int h = 0; h < 2; h++) {
                int r = mt * 16 + g + 8 * h;
                float2 st = stats[r];
                float* orow = g_h1 + ((size_t)b * LL + l0 + r) * CC;
#pragma unroll
                for (int nt = 0; nt < 4; nt++) {
                    float2 o;
                    o.x = f2tff((v[mt][h][nt * 2]     - st.x) * st.y * ga[nt * 2]     + be[nt * 2]);
                    o.y = f2tff((v[mt][h][nt * 2 + 1] - st.x) * st.y * ga[nt * 2 + 1] + be[nt * 2 + 1]);
                    *(float2*)(orow + n0 + nt * 8 + 2 * q) = o;
                }
            }
    } else {
        float* dred = sA + 2048;                   // [64][8]
#pragma unroll
        for (int mt = 0; mt < 4; mt++)
#pragma unroll
            for (int h = 0; h < 2; h++) {
                int r = mt * 16 + g + 8 * h;
                float2 st = stats[r];
                float d = 0.f;
#pragma unroll
                for (int p = 0; p < 8; p++)
                    d += ((v[mt][h][p] - st.x) * st.y * ga[p] + be[p]) * lw[p];
                d += __shfl_xor_sync(0xffffffffu, d, 1);
                d += __shfl_xor_sync(0xffffffffu, d, 2);
                if (q == 0) dred[r * 8 + warp] = d;
            }
        __syncthreads();
        if (tid < 64) {
            float d = 0.f;
#pragma unroll
            for (int wv = 0; wv < 8; wv++) d += dred[tid * 8 + wv];
            predout[b * LL + l0 + tid] = d + __ldg(linb);
        }
    }
}

// ---------------------------------------------------------------------------
extern "C" void kernel_launch(void* const* d_in, const int* in_sizes, int n_in,
                              void* d_out, int out_size)
{
    const float* x    = (const float*)d_in[0];
    const int*   dur  = (const int*)d_in[1];
    const float* c1w  = (const float*)d_in[2];
    const float* c1b  = (const float*)d_in[3];
    const float* ln1g = (const float*)d_in[4];
    const float* ln1b = (const float*)d_in[5];
    const float* c2w  = (const float*)d_in[6];
    const float* c2b  = (const float*)d_in[7];
    const float* ln2g = (const float*)d_in[8];
    const float* ln2b = (const float*)d_in[9];
    const float* linw = (const float*)d_in[10];
    const float* linb = (const float*)d_in[11];

    float* out  = (float*)d_out;
    float* pred = out + (size_t)BB * MEL * CC;

    cudaFuncSetAttribute(conv_mma_kernel<false>,
                         cudaFuncAttributeMaxDynamicSharedMemorySize, SMEM_BYTES);
    cudaFuncSetAttribute(conv_mma_kernel<true>,
                         cudaFuncAttributeMaxDynamicSharedMemorySize, SMEM_BYTES);

    cvt_weights<<<192, 512>>>(c1w, c2w);
    cumsum_kernel<<<BB, 512>>>(dur);

    dim3 cgrid(LL / 64, BB);
    conv_mma_kernel<false><<<cgrid, 256, SMEM_BYTES>>>(x, c1b, ln1g, ln1b,
                                                       nullptr, nullptr, nullptr, out);
    conv_mma_kernel<true><<<cgrid, 256, SMEM_BYTES>>>(x, c2b, ln2g, ln2b,
                                                      linw, linb, pred, nullptr);
}